// round 4
// baseline (speedup 1.0000x reference)
#include <cuda_runtime.h>

#define DIM 64
#define MAXK 512
#define TPB 512

typedef unsigned long long u64;

__device__ float g_esq[MAXK];
__device__ float g_partials[8192];

__device__ __forceinline__ void fma2(u64 &acc, u64 a, u64 b) {
    asm("fma.rn.f32x2 %0, %1, %2, %0;" : "+l"(acc) : "l"(a), "l"(b));
}
__device__ __forceinline__ float2 asf2(u64 v) {
    float2 r; asm("mov.b64 {%0, %1}, %2;" : "=f"(r.x), "=f"(r.y) : "l"(v)); return r;
}
__device__ __forceinline__ u64 packf2(float lo, float hi) {
    u64 r; asm("mov.b64 %0, {%1, %2};" : "=l"(r) : "f"(lo), "f"(hi)); return r;
}

// Per-code squared norms, replicating jnp.sum(e*e, axis=1) rounding:
// elementwise fl(e*e), then strictly sequential fp32 sum (no FMA contraction).
__global__ void vq_prep(const float* __restrict__ cb, int K) {
    int k = blockIdx.x * blockDim.x + threadIdx.x;
    if (k < K) {
        float s = 0.f;
        const float* e = cb + (long)k * DIM;
#pragma unroll
        for (int d = 0; d < DIM; d++)
            s = __fadd_rn(s, __fmul_rn(e[d], e[d]));
        g_esq[k] = s;
    }
}

__global__ __launch_bounds__(TPB, 1) void vq_main(
    const float* __restrict__ x, const float* __restrict__ cb,
    float* __restrict__ out, int N, int K,
    long q_off, long idx_off, int do_loss)
{
    extern __shared__ float sm[];      // [K*DIM] codebook + [K] esq
    float* scb  = sm;
    float* sesq = sm + (long)K * DIM;
    int tid = threadIdx.x;

    // Cooperative stage of codebook + norms into smem (16B copies).
    {
        int tot4 = K * DIM / 4;
        float4* s4 = reinterpret_cast<float4*>(scb);
        const float4* g4 = reinterpret_cast<const float4*>(cb);
        for (int i = tid; i < tot4; i += blockDim.x) s4[i] = g4[i];
        for (int i = tid; i < K; i += blockDim.x) sesq[i] = g_esq[i];
    }
    __syncthreads();

    long row = (long)blockIdx.x * blockDim.x + tid;
    float lsum = 0.f;
    int   bidx = 0;

    if (row < N) {
        // x row -> packed f32x2 register pairs; x_sq replicated sequentially.
        u64   xp[DIM / 2];
        float x_sq = 0.f;
#pragma unroll
        for (int i = 0; i < DIM / 4; i++) {
            float4 v = *reinterpret_cast<const float4*>(x + row * DIM + i * 4);
            xp[2 * i]     = packf2(v.x, v.y);
            xp[2 * i + 1] = packf2(v.z, v.w);
            x_sq = __fadd_rn(x_sq, __fmul_rn(v.x, v.x));
            x_sq = __fadd_rn(x_sq, __fmul_rn(v.y, v.y));
            x_sq = __fadd_rn(x_sq, __fmul_rn(v.z, v.z));
            x_sq = __fadd_rn(x_sq, __fmul_rn(v.w, v.w));
        }

        float best = 3.4e38f;
#pragma unroll 2
        for (int k = 0; k < K; k++) {
            const ulonglong2* e2 = reinterpret_cast<const ulonglong2*>(scb + (long)k * DIM);
            u64 a0 = 0ull, a1 = 0ull, a2 = 0ull, a3 = 0ull;
#pragma unroll
            for (int i = 0; i < DIM / 4; i++) {         // 16 iters: LDS.128 + 2x FFMA2 each
                ulonglong2 e = e2[i];                   // dims 4i..4i+3 (two packed pairs)
                if (i & 1) { fma2(a2, xp[2 * i], e.x); fma2(a3, xp[2 * i + 1], e.y); }
                else       { fma2(a0, xp[2 * i], e.x); fma2(a1, xp[2 * i + 1], e.y); }
            }
            float2 f0 = asf2(a0), f1 = asf2(a1), f2 = asf2(a2), f3 = asf2(a3);
            float dot = ((f0.x + f0.y) + (f1.x + f1.y)) + ((f2.x + f2.y) + (f3.x + f3.y));
            // Replicate reference rounding: fl(fl(x_sq + e_sq) - fl(2*dot)).
            float s = __fsub_rn(__fadd_rn(x_sq, sesq[k]), __fmul_rn(2.0f, dot));
            if (s < best) { best = s; bidx = k; }       // strict < : first-occurrence argmin
        }

        // Epilogue: winner code from GLOBAL; quantized_st = fl(x + fl(e - x)).
        const float4* eq = reinterpret_cast<const float4*>(cb + (long)bidx * DIM);
        bool q_vec = (q_off >= 0) && ((q_off & 3) == 0);
#pragma unroll
        for (int i = 0; i < DIM / 4; i++) {
            float4 e = eq[i];
            float2 lo = asf2(xp[2 * i]), hi = asf2(xp[2 * i + 1]);
            float d0 = __fsub_rn(e.x, lo.x), d1 = __fsub_rn(e.y, lo.y);
            float d2 = __fsub_rn(e.z, hi.x), d3 = __fsub_rn(e.w, hi.y);
            lsum += d0 * d0 + d1 * d1 + d2 * d2 + d3 * d3;
            if (q_off >= 0) {
                float4 st;
                st.x = __fadd_rn(lo.x, d0); st.y = __fadd_rn(lo.y, d1);
                st.z = __fadd_rn(hi.x, d2); st.w = __fadd_rn(hi.y, d3);
                float* dst = out + q_off + row * DIM + i * 4;
                if (q_vec) {
                    *reinterpret_cast<float4*>(dst) = st;
                } else {                                 // q_off==1: only 4B-aligned
                    dst[0] = st.x; dst[1] = st.y; dst[2] = st.z; dst[3] = st.w;
                }
            }
        }
        if (idx_off >= 0) out[idx_off + row] = (float)bidx;
    }

    if (do_loss) {
        __syncthreads();              // smem codebook no longer needed; reuse for reduce
        sm[tid] = lsum;
        __syncthreads();
#pragma unroll
        for (int o = TPB / 2; o > 0; o >>= 1) {
            if (tid < o) sm[tid] += sm[tid + o];
            __syncthreads();
        }
        if (tid == 0) g_partials[blockIdx.x] = sm[0];
    }
}

__global__ void vq_final(float* out, int nblocks, float scale) {
    __shared__ float s[1024];
    int tid = threadIdx.x;
    float v = 0.f;
    for (int i = tid; i < nblocks; i += blockDim.x) v += g_partials[i];  // fixed order
    s[tid] = v;
    __syncthreads();
    for (int o = blockDim.x / 2; o > 0; o >>= 1) {
        if (tid < o) s[tid] += s[tid + o];
        __syncthreads();
    }
    if (tid == 0) out[0] = s[0] * scale;
}

extern "C" void kernel_launch(void* const* d_in, const int* in_sizes, int n_in,
                              void* d_out, int out_size) {
    const float* a = (const float*)d_in[0];
    const float* b = (const float*)d_in[1];
    long s0 = in_sizes[0], s1 = in_sizes[1];
    const float *x, *cb; long xs, cs;
    if (s0 >= s1) { x = a; xs = s0; cb = b; cs = s1; }
    else          { x = b; xs = s1; cb = a; cs = s0; }

    int K = (int)(cs / DIM);
    int N = (int)(xs / DIM);
    long QN = (long)N * DIM;
    long osz = (long)out_size;

    // Output layout dispatch (tuple order: loss, quantized_st, encoding_indices)
    long loss_off = -1, q_off = -1, idx_off = -1;
    if      (osz == 1 + QN + N) { loss_off = 0; q_off = 1; idx_off = 1 + QN; }
    else if (osz == QN + N)     { q_off = 0; idx_off = QN; }
    else if (osz == QN)         { q_off = 0; }
    else if (osz == N)          { idx_off = 0; }
    else if (osz == 1)          { loss_off = 0; }
    else                        { loss_off = 0; q_off = 1; idx_off = 1 + QN; }

    float* out = (float*)d_out;
    int do_loss = (loss_off >= 0) ? 1 : 0;

    size_t smem = ((size_t)K * DIM + K) * sizeof(float);
    cudaFuncSetAttribute(vq_main, cudaFuncAttributeMaxDynamicSharedMemorySize, (int)smem);

    vq_prep<<<(K + 511) / 512, 512>>>(cb, K);
    int blocks = (N + TPB - 1) / TPB;
    vq_main<<<blocks, TPB, smem>>>(x, cb, out, N, K, q_off, idx_off, do_loss);
    if (do_loss) {
        float scale = (float)(1.25 / ((double)N * (double)DIM));
        vq_final<<<1, 1024>>>(out + loss_off, blocks, scale);
    }
}

// round 5
// speedup vs baseline: 1.1678x; 1.1678x over previous
#include <cuda_runtime.h>

#define DIM 64
#define MAXK 512
#define TPB 256
#define ROWS_PER_T 2
#define CODES_PER_G 8
#define ROWS_PER_B (TPB * ROWS_PER_T)

typedef unsigned long long u64;

__device__ float g_partials[8192];

__device__ __forceinline__ void fma2(u64 &acc, u64 a, u64 b) {
    asm("fma.rn.f32x2 %0, %1, %2, %0;" : "+l"(acc) : "l"(a), "l"(b));
}
__device__ __forceinline__ float2 asf2(u64 v) {
    float2 r; asm("mov.b64 {%0, %1}, %2;" : "=f"(r.x), "=f"(r.y) : "l"(v)); return r;
}
__device__ __forceinline__ u64 packf2(float lo, float hi) {
    u64 r; asm("mov.b64 %0, {%1, %2};" : "=l"(r) : "f"(lo), "f"(hi)); return r;
}

__global__ __launch_bounds__(TPB, 1) void vq_main(
    const float* __restrict__ x, const float* __restrict__ cb,
    float* __restrict__ out, int N, int K,
    long q_off, long idx_off, int do_loss)
{
    extern __shared__ float sm[];      // [K*DIM] codebook + [K] esq
    float* scb  = sm;
    float* sesq = sm + (long)K * DIM;
    int tid = threadIdx.x;

    // Stage codebook into smem (16B copies).
    {
        int tot4 = K * DIM / 4;
        float4* s4 = reinterpret_cast<float4*>(scb);
        const float4* g4 = reinterpret_cast<const float4*>(cb);
        for (int i = tid; i < tot4; i += TPB) s4[i] = g4[i];
    }
    // e_sq in-block from GLOBAL (L2-resident), replicating jnp.sum(e*e) rounding:
    // elementwise fl(e*e), strictly sequential fp32 adds.
    for (int k = tid; k < K; k += TPB) {
        const float* e = cb + (long)k * DIM;
        float s = 0.f;
#pragma unroll
        for (int d = 0; d < DIM; d++)
            s = __fadd_rn(s, __fmul_rn(e[d], e[d]));
        sesq[k] = s;
    }
    __syncthreads();

    long row0 = (long)blockIdx.x * ROWS_PER_B + tid;          // thread's row A
    long row1 = row0 + TPB;                                   // thread's row B
    bool v0 = row0 < N, v1 = row1 < N;

    // Two x rows fully in registers as packed f32x2; x_sq sequential rounding.
    u64 xp0[DIM / 2], xp1[DIM / 2];
    float xsq0 = 0.f, xsq1 = 0.f;
#pragma unroll
    for (int i = 0; i < DIM / 4; i++) {
        float4 a = v0 ? *reinterpret_cast<const float4*>(x + row0 * DIM + i * 4)
                      : make_float4(0.f, 0.f, 0.f, 0.f);
        float4 b = v1 ? *reinterpret_cast<const float4*>(x + row1 * DIM + i * 4)
                      : make_float4(0.f, 0.f, 0.f, 0.f);
        xp0[2 * i] = packf2(a.x, a.y); xp0[2 * i + 1] = packf2(a.z, a.w);
        xp1[2 * i] = packf2(b.x, b.y); xp1[2 * i + 1] = packf2(b.z, b.w);
        xsq0 = __fadd_rn(xsq0, __fmul_rn(a.x, a.x));
        xsq0 = __fadd_rn(xsq0, __fmul_rn(a.y, a.y));
        xsq0 = __fadd_rn(xsq0, __fmul_rn(a.z, a.z));
        xsq0 = __fadd_rn(xsq0, __fmul_rn(a.w, a.w));
        xsq1 = __fadd_rn(xsq1, __fmul_rn(b.x, b.x));
        xsq1 = __fadd_rn(xsq1, __fmul_rn(b.y, b.y));
        xsq1 = __fadd_rn(xsq1, __fmul_rn(b.z, b.z));
        xsq1 = __fadd_rn(xsq1, __fmul_rn(b.w, b.w));
    }

    float best0 = 3.4e38f, best1 = 3.4e38f;
    int   bidx0 = 0,       bidx1 = 0;

#pragma unroll 1
    for (int k0 = 0; k0 < K; k0 += CODES_PER_G) {
        u64 acc0[CODES_PER_G], acc1[CODES_PER_G];
#pragma unroll
        for (int c = 0; c < CODES_PER_G; c++) { acc0[c] = 0ull; acc1[c] = 0ull; }

#pragma unroll
        for (int i = 0; i < DIM / 4; i++) {               // 16 chunks of 4 dims
            ulonglong2 e[CODES_PER_G];
#pragma unroll
            for (int c = 0; c < CODES_PER_G; c++)          // broadcast LDS.128
                e[c] = *reinterpret_cast<const ulonglong2*>(scb + (k0 + c) * DIM + i * 4);
#pragma unroll
            for (int c = 0; c < CODES_PER_G; c++) {
                fma2(acc0[c], xp0[2 * i], e[c].x);
                fma2(acc0[c], xp0[2 * i + 1], e[c].y);
                fma2(acc1[c], xp1[2 * i], e[c].x);
                fma2(acc1[c], xp1[2 * i + 1], e[c].y);
            }
        }
        // Scores: fl(fl(x_sq + e_sq) - fl(2*dot)); first-occurrence argmin (c ascending).
#pragma unroll
        for (int c = 0; c < CODES_PER_G; c++) {
            float eq = sesq[k0 + c];
            float2 f0 = asf2(acc0[c]);
            float d0 = f0.x + f0.y;
            float s0 = __fsub_rn(__fadd_rn(xsq0, eq), __fmul_rn(2.0f, d0));
            if (s0 < best0) { best0 = s0; bidx0 = k0 + c; }
            float2 f1 = asf2(acc1[c]);
            float d1 = f1.x + f1.y;
            float s1 = __fsub_rn(__fadd_rn(xsq1, eq), __fmul_rn(2.0f, d1));
            if (s1 < best1) { best1 = s1; bidx1 = k0 + c; }
        }
    }

    // Epilogue: winner code from GLOBAL (L2-hit); quantized_st = fl(x + fl(e - x)).
    float lsum = 0.f;
    bool q_vec = (q_off >= 0) && ((q_off & 3) == 0);
#pragma unroll 1
    for (int r = 0; r < ROWS_PER_T; r++) {
        long row  = r ? row1 : row0;
        int  bidx = r ? bidx1 : bidx0;
        u64* xp   = r ? xp1 : xp0;
        if (row >= N) break;
        const float4* eq = reinterpret_cast<const float4*>(cb + (long)bidx * DIM);
#pragma unroll
        for (int i = 0; i < DIM / 4; i++) {
            float4 e = eq[i];
            float2 lo = asf2(xp[2 * i]), hi = asf2(xp[2 * i + 1]);
            float d0 = __fsub_rn(e.x, lo.x), d1 = __fsub_rn(e.y, lo.y);
            float d2 = __fsub_rn(e.z, hi.x), d3 = __fsub_rn(e.w, hi.y);
            lsum += d0 * d0 + d1 * d1 + d2 * d2 + d3 * d3;
            if (q_off >= 0) {
                float* dst = out + q_off + row * DIM + i * 4;
                if (q_vec) {
                    float4 st = make_float4(__fadd_rn(lo.x, d0), __fadd_rn(lo.y, d1),
                                            __fadd_rn(hi.x, d2), __fadd_rn(hi.y, d3));
                    *reinterpret_cast<float4*>(dst) = st;
                } else {                                   // q_off==1: 4B-aligned only
                    dst[0] = __fadd_rn(lo.x, d0); dst[1] = __fadd_rn(lo.y, d1);
                    dst[2] = __fadd_rn(hi.x, d2); dst[3] = __fadd_rn(hi.y, d3);
                }
            }
        }
        if (idx_off >= 0) out[idx_off + row] = (float)bidx;
    }

    if (do_loss) {
        __syncthreads();              // codebook smem dead; reuse for reduction
        sm[tid] = lsum;
        __syncthreads();
#pragma unroll
        for (int o = TPB / 2; o > 0; o >>= 1) {
            if (tid < o) sm[tid] += sm[tid + o];
            __syncthreads();
        }
        if (tid == 0) g_partials[blockIdx.x] = sm[0];
    }
}

__global__ void vq_final(float* out, int nblocks, float scale) {
    __shared__ float s[1024];
    int tid = threadIdx.x;
    float v = 0.f;
    for (int i = tid; i < nblocks; i += blockDim.x) v += g_partials[i];  // fixed order
    s[tid] = v;
    __syncthreads();
    for (int o = blockDim.x / 2; o > 0; o >>= 1) {
        if (tid < o) s[tid] += s[tid + o];
        __syncthreads();
    }
    if (tid == 0) out[0] = s[0] * scale;
}

extern "C" void kernel_launch(void* const* d_in, const int* in_sizes, int n_in,
                              void* d_out, int out_size) {
    const float* a = (const float*)d_in[0];
    const float* b = (const float*)d_in[1];
    long s0 = in_sizes[0], s1 = in_sizes[1];
    const float *x, *cb; long xs, cs;
    if (s0 >= s1) { x = a; xs = s0; cb = b; cs = s1; }
    else          { x = b; xs = s1; cb = a; cs = s0; }

    int K = (int)(cs / DIM);
    int N = (int)(xs / DIM);
    long QN = (long)N * DIM;
    long osz = (long)out_size;

    // Output layout (confirmed R3/R4): [loss(1), quantized_st(QN), indices(N)]
    long loss_off = -1, q_off = -1, idx_off = -1;
    if      (osz == 1 + QN + N) { loss_off = 0; q_off = 1; idx_off = 1 + QN; }
    else if (osz == QN + N)     { q_off = 0; idx_off = QN; }
    else if (osz == QN)         { q_off = 0; }
    else if (osz == N)          { idx_off = 0; }
    else if (osz == 1)          { loss_off = 0; }
    else                        { loss_off = 0; q_off = 1; idx_off = 1 + QN; }

    float* out = (float*)d_out;
    int do_loss = (loss_off >= 0) ? 1 : 0;

    size_t smem = ((size_t)K * DIM + K) * sizeof(float);
    cudaFuncSetAttribute(vq_main, cudaFuncAttributeMaxDynamicSharedMemorySize, (int)smem);

    int blocks = (N + ROWS_PER_B - 1) / ROWS_PER_B;
    vq_main<<<blocks, TPB, smem>>>(x, cb, out, N, K, q_off, idx_off, do_loss);
    if (do_loss) {
        float scale = (float)(1.25 / ((double)N * (double)DIM));
        vq_final<<<1, 1024>>>(out + loss_off, blocks, scale);
    }
}